// round 10
// baseline (speedup 1.0000x reference)
#include <cuda_runtime.h>

// SMorph: out = sum_k (x_p+f_k) e^{a(x_p+f_k)} / sum_k e^{a(x_p+f_k)}
// Factored: G=exp(a*x), H=x*G, E_k=exp(a*f_k), F_k=f_k*E_k
//   num = sum_k E_k*H + F_k*G;  den = sum_k E_k*G
// Scalar FFMA + y-register-reuse: each thread computes a 4x2 output patch;
// the 8 input rows of its footprint are loaded from smem ONCE each and
// applied to both output rows (tap row r -> out0, r-1 -> out1): -43% LDS.
// Warp = 4 row-pairs x 8 lanes -> conflict-free LDS.32 vs PITCH=71.
// Output stores: 2x STG.64 (row base only 8B-aligned since WO=186).

namespace {
constexpr int BATCH = 8;
constexpr int HH = 192, WW = 192;
constexpr int CO = 8;
constexpr int KH = 7, KW = 7;
constexpr int HO = 186, WO = 186;

constexpr int TILE_X = 64;
constexpr int TILE_Y = 32;           // 2 rows per thread
constexpr int ITX = TILE_X + KW - 1; // 70
constexpr int ITY = TILE_Y + KH - 1; // 38
constexpr int PITCH = 71;
constexpr int OPT = 4;               // outputs per thread in x
constexpr int WINW = OPT + KW - 1;   // 10
}

__global__ __launch_bounds__(256, 4)
void smorph_kernel(const float* __restrict__ x,
                   const float* __restrict__ filt,
                   const float* __restrict__ alpha,
                   float* __restrict__ out)
{
    __shared__ float sG[ITY * PITCH];
    __shared__ float sH[ITY * PITCH];
    __shared__ float2 sEF[KH * KW];   // {E, F} per tap

    const int bc  = blockIdx.z;       // b*8 + c
    const int c   = bc & 7;
    const int tid = threadIdx.x;

    const float a = alpha[c];

    if (tid < KH * KW) {
        float f = filt[c * (KH * KW) + tid];
        float e = __expf(a * f);
        sEF[tid] = make_float2(e, f * e);
    }

    const int gx0 = blockIdx.x * TILE_X;
    const int gy0 = blockIdx.y * TILE_Y;
    const float* xb = x + (bc >> 3) * (HH * WW);

    // Cooperative tile fill: G = exp(a*x), H = x*G
    for (int i = tid; i < ITY * ITX; i += 256) {
        int iy = i / ITX;
        int ix = i - iy * ITX;
        int gy = gy0 + iy;
        int gx = gx0 + ix;
        float v = (gy < HH && gx < WW) ? xb[gy * WW + gx] : 0.0f;
        float g = __expf(a * v);
        sG[iy * PITCH + ix] = g;
        sH[iy * PITCH + ix] = v * g;
    }
    __syncthreads();

    // Warp geometry: 4 row-pairs x 8 lanes; thread owns 4 cols x 2 rows.
    const int lane = tid & 31;
    const int warp = tid >> 5;        // 0..7
    const int tx = lane & 7;          // 0..7
    const int sy = lane >> 3;         // 0..3
    const int wx = warp & 1;          // 0..1
    const int wy = warp >> 1;         // 0..3
    const int lx = (wx * 8 + tx) * OPT;     // 0..60
    const int ly = (wy * 4 + sy) * 2;       // 0,2,..,30 (first output row)

    float accN[2][OPT], accD[2][OPT];
    #pragma unroll
    for (int r = 0; r < 2; r++)
        #pragma unroll
        for (int o = 0; o < OPT; o++) { accN[r][o] = 0.f; accD[r][o] = 0.f; }

    // Loop over the 8 input rows of this thread's footprint; load once,
    // feed both output rows.
    #pragma unroll
    for (int r = 0; r < KH + 1; r++) {
        const float* gr = &sG[(ly + r) * PITCH + lx];
        const float* hr = &sH[(ly + r) * PITCH + lx];
        float g[WINW], h[WINW];
        #pragma unroll
        for (int j = 0; j < WINW; j++) {
            g[j] = gr[j];
            h[j] = hr[j];
        }

        // out-row 0 uses tap row r (valid for r = 0..6)
        if (r <= KH - 1) {
            #pragma unroll
            for (int kx = 0; kx < KW; kx++) {
                const float2 ef = sEF[r * KW + kx];   // broadcast
                const float E = ef.x, F = ef.y;
                #pragma unroll
                for (int o = 0; o < OPT; o++) {
                    accN[0][o] = fmaf(E, h[kx + o], fmaf(F, g[kx + o], accN[0][o]));
                    accD[0][o] = fmaf(E, g[kx + o], accD[0][o]);
                }
            }
        }
        // out-row 1 uses tap row r-1 (valid for r = 1..7)
        if (r >= 1) {
            #pragma unroll
            for (int kx = 0; kx < KW; kx++) {
                const float2 ef = sEF[(r - 1) * KW + kx];   // broadcast
                const float E = ef.x, F = ef.y;
                #pragma unroll
                for (int o = 0; o < OPT; o++) {
                    accN[1][o] = fmaf(E, h[kx + o], fmaf(F, g[kx + o], accN[1][o]));
                    accD[1][o] = fmaf(E, g[kx + o], accD[1][o]);
                }
            }
        }
    }

    const int ox = gx0 + lx;
    #pragma unroll
    for (int r = 0; r < 2; r++) {
        const int oy = gy0 + ly + r;
        if (oy < HO) {
            float* orow = out + ((long)bc * HO + oy) * WO;
            float v0 = __fdividef(accN[r][0], accD[r][0]);
            float v1 = __fdividef(accN[r][1], accD[r][1]);
            float v2 = __fdividef(accN[r][2], accD[r][2]);
            float v3 = __fdividef(accN[r][3], accD[r][3]);
            if (ox + 3 < WO) {
                // row base is 8B-aligned (WO=186 even), never 16B for odd oy:
                // use two STG.64.
                *reinterpret_cast<float2*>(orow + ox)     = make_float2(v0, v1);
                *reinterpret_cast<float2*>(orow + ox + 2) = make_float2(v2, v3);
            } else {
                if (ox + 0 < WO) orow[ox + 0] = v0;
                if (ox + 1 < WO) orow[ox + 1] = v1;
                if (ox + 2 < WO) orow[ox + 2] = v2;
                if (ox + 3 < WO) orow[ox + 3] = v3;
            }
        }
    }
}

extern "C" void kernel_launch(void* const* d_in, const int* in_sizes, int n_in,
                              void* d_out, int out_size) {
    const float* x     = (const float*)d_in[0];   // (8,1,192,192)
    const float* filt  = (const float*)d_in[1];   // (8,1,7,7)
    const float* alpha = (const float*)d_in[2];   // (8,1)
    float* out = (float*)d_out;                   // (8,8,186,186)

    dim3 block(256);
    dim3 grid((WO + TILE_X - 1) / TILE_X,   // 3
              (HO + TILE_Y - 1) / TILE_Y,   // 6
              BATCH * CO);                  // 64
    smorph_kernel<<<grid, block>>>(x, filt, alpha, out);
}

// round 11
// speedup vs baseline: 1.0115x; 1.0115x over previous
#include <cuda_runtime.h>

// SMorph: out = sum_k (x_p+f_k) e^{a(x_p+f_k)} / sum_k e^{a(x_p+f_k)}
// Factored: G=exp(a*x), H=x*G, E_k=exp(a*f_k), F_k=f_k*E_k
//   num = sum_k E_k*H + F_k*G;  den = sum_k E_k*G
// Scalar FFMA + y-register-reuse: each thread computes a 4x2 output patch;
// the 8 input rows of its footprint are loaded from smem ONCE each and
// applied to both output rows (tap row r -> out0, r-1 -> out1): -43% LDS.
// Warp = 4 row-pairs x 8 lanes -> conflict-free LDS.32 vs PITCH=71.
// Output stores: 2x STG.64 (row base only 8B-aligned since WO=186).

namespace {
constexpr int BATCH = 8;
constexpr int HH = 192, WW = 192;
constexpr int CO = 8;
constexpr int KH = 7, KW = 7;
constexpr int HO = 186, WO = 186;

constexpr int TILE_X = 64;
constexpr int TILE_Y = 32;           // 2 rows per thread
constexpr int ITX = TILE_X + KW - 1; // 70
constexpr int ITY = TILE_Y + KH - 1; // 38
constexpr int PITCH = 71;
constexpr int OPT = 4;               // outputs per thread in x
constexpr int WINW = OPT + KW - 1;   // 10
}

__global__ __launch_bounds__(256, 4)
void smorph_kernel(const float* __restrict__ x,
                   const float* __restrict__ filt,
                   const float* __restrict__ alpha,
                   float* __restrict__ out)
{
    __shared__ float sG[ITY * PITCH];
    __shared__ float sH[ITY * PITCH];
    __shared__ float2 sEF[KH * KW];   // {E, F} per tap

    const int bc  = blockIdx.z;       // b*8 + c
    const int c   = bc & 7;
    const int tid = threadIdx.x;

    const float a = alpha[c];

    if (tid < KH * KW) {
        float f = filt[c * (KH * KW) + tid];
        float e = __expf(a * f);
        sEF[tid] = make_float2(e, f * e);
    }

    const int gx0 = blockIdx.x * TILE_X;
    const int gy0 = blockIdx.y * TILE_Y;
    const float* xb = x + (bc >> 3) * (HH * WW);

    // Cooperative tile fill: G = exp(a*x), H = x*G
    for (int i = tid; i < ITY * ITX; i += 256) {
        int iy = i / ITX;
        int ix = i - iy * ITX;
        int gy = gy0 + iy;
        int gx = gx0 + ix;
        float v = (gy < HH && gx < WW) ? xb[gy * WW + gx] : 0.0f;
        float g = __expf(a * v);
        sG[iy * PITCH + ix] = g;
        sH[iy * PITCH + ix] = v * g;
    }
    __syncthreads();

    // Warp geometry: 4 row-pairs x 8 lanes; thread owns 4 cols x 2 rows.
    const int lane = tid & 31;
    const int warp = tid >> 5;        // 0..7
    const int tx = lane & 7;          // 0..7
    const int sy = lane >> 3;         // 0..3
    const int wx = warp & 1;          // 0..1
    const int wy = warp >> 1;         // 0..3
    const int lx = (wx * 8 + tx) * OPT;     // 0..60
    const int ly = (wy * 4 + sy) * 2;       // 0,2,..,30 (first output row)

    float accN[2][OPT], accD[2][OPT];
    #pragma unroll
    for (int r = 0; r < 2; r++)
        #pragma unroll
        for (int o = 0; o < OPT; o++) { accN[r][o] = 0.f; accD[r][o] = 0.f; }

    // Loop over the 8 input rows of this thread's footprint; load once,
    // feed both output rows.
    #pragma unroll
    for (int r = 0; r < KH + 1; r++) {
        const float* gr = &sG[(ly + r) * PITCH + lx];
        const float* hr = &sH[(ly + r) * PITCH + lx];
        float g[WINW], h[WINW];
        #pragma unroll
        for (int j = 0; j < WINW; j++) {
            g[j] = gr[j];
            h[j] = hr[j];
        }

        // out-row 0 uses tap row r (valid for r = 0..6)
        if (r <= KH - 1) {
            #pragma unroll
            for (int kx = 0; kx < KW; kx++) {
                const float2 ef = sEF[r * KW + kx];   // broadcast
                const float E = ef.x, F = ef.y;
                #pragma unroll
                for (int o = 0; o < OPT; o++) {
                    accN[0][o] = fmaf(E, h[kx + o], fmaf(F, g[kx + o], accN[0][o]));
                    accD[0][o] = fmaf(E, g[kx + o], accD[0][o]);
                }
            }
        }
        // out-row 1 uses tap row r-1 (valid for r = 1..7)
        if (r >= 1) {
            #pragma unroll
            for (int kx = 0; kx < KW; kx++) {
                const float2 ef = sEF[(r - 1) * KW + kx];   // broadcast
                const float E = ef.x, F = ef.y;
                #pragma unroll
                for (int o = 0; o < OPT; o++) {
                    accN[1][o] = fmaf(E, h[kx + o], fmaf(F, g[kx + o], accN[1][o]));
                    accD[1][o] = fmaf(E, g[kx + o], accD[1][o]);
                }
            }
        }
    }

    const int ox = gx0 + lx;
    #pragma unroll
    for (int r = 0; r < 2; r++) {
        const int oy = gy0 + ly + r;
        if (oy < HO) {
            float* orow = out + ((long)bc * HO + oy) * WO;
            float v0 = __fdividef(accN[r][0], accD[r][0]);
            float v1 = __fdividef(accN[r][1], accD[r][1]);
            float v2 = __fdividef(accN[r][2], accD[r][2]);
            float v3 = __fdividef(accN[r][3], accD[r][3]);
            if (ox + 3 < WO) {
                // row base is 8B-aligned (WO=186 even), never 16B for odd oy:
                // use two STG.64.
                *reinterpret_cast<float2*>(orow + ox)     = make_float2(v0, v1);
                *reinterpret_cast<float2*>(orow + ox + 2) = make_float2(v2, v3);
            } else {
                if (ox + 0 < WO) orow[ox + 0] = v0;
                if (ox + 1 < WO) orow[ox + 1] = v1;
                if (ox + 2 < WO) orow[ox + 2] = v2;
                if (ox + 3 < WO) orow[ox + 3] = v3;
            }
        }
    }
}

extern "C" void kernel_launch(void* const* d_in, const int* in_sizes, int n_in,
                              void* d_out, int out_size) {
    const float* x     = (const float*)d_in[0];   // (8,1,192,192)
    const float* filt  = (const float*)d_in[1];   // (8,1,7,7)
    const float* alpha = (const float*)d_in[2];   // (8,1)
    float* out = (float*)d_out;                   // (8,8,186,186)

    dim3 block(256);
    dim3 grid((WO + TILE_X - 1) / TILE_X,   // 3
              (HO + TILE_Y - 1) / TILE_Y,   // 6
              BATCH * CO);                  // 64
    smorph_kernel<<<grid, block>>>(x, filt, alpha, out);
}